// round 1
// baseline (speedup 1.0000x reference)
#include <cuda_runtime.h>
#include <cstddef>

#define NN 100000
#define NE 600000
#define NF 64
#define EF 16
#define EH 128
#define NSTEPS 6

// ---- scratch (device globals; no allocation allowed) ----
__device__ float g_P [(size_t)NN * EH];   // nf@W1 + b1          (51 MB)
__device__ float g_U1[(size_t)NN * EH];   // nf@U1 + b1          (51 MB)
__device__ float g_B [(size_t)NE * EH];   // loop-invariant bias (307 MB)
__device__ float g_G [(size_t)NE * EH];   // h@W3                (307 MB)
__device__ float g_T [(size_t)NN * EH];   // segment_sum(g,from) (51 MB)
__device__ float g_H0[(size_t)NE * EH];   // h ping              (307 MB)
__device__ float g_H1[(size_t)NE * EH];   // h pong              (307 MB)

// ============================================================
// Tiled fp32 GEMM: C[M,128] = A[M,KTOT] @ W[KTOT,128]  (+epilogues)
// 256 threads, 128x128 tile, 8x8 per thread, K-chunks of min(KTOT,32).
// EPI 0: C = acc + bias                               (store)
// EPI 1: C = acc + bias + gadd[gidx[row]]             (store, gather-add)
// EPI 2: C = acc (store)  AND  atomicAdd acc_out[gidx[row]] += acc
// EPI 3: atomicAdd acc_out[gidx[row]] += acc + bias   (no store)
// ============================================================
template <int KTOT, int EPI>
__global__ void __launch_bounds__(256)
gemm_tile(const float* __restrict__ A, const float* __restrict__ W,
          const float* __restrict__ bias, float* __restrict__ C, int M,
          const int* __restrict__ gidx, const float* __restrict__ gadd,
          float* __restrict__ acc_out)
{
    constexpr int KC = (KTOT < 32) ? KTOT : 32;
    __shared__ float As[KC][132];   // [k][row], padded vs bank conflicts
    __shared__ float Ws[KC][128];   // [k][col]

    const int tid = threadIdx.x;
    const int tr  = tid >> 4;       // 0..15 (row group)
    const int tc  = tid & 15;       // 0..15 (col group)
    const int r0  = blockIdx.x * 128;

    float acc[8][8];
#pragma unroll
    for (int i = 0; i < 8; ++i)
#pragma unroll
        for (int j = 0; j < 8; ++j) acc[i][j] = 0.f;

    for (int kc0 = 0; kc0 < KTOT; kc0 += KC) {
        __syncthreads();
        // load A tile (transposed into smem)
#pragma unroll
        for (int i = 0; i < KC / 8; ++i) {
            int f  = tid + i * 256;
            int r  = f / (KC / 4);
            int c4 = (f % (KC / 4)) * 4;
            float4 v = make_float4(0.f, 0.f, 0.f, 0.f);
            int gr = r0 + r;
            if (gr < M) v = *(const float4*)(A + (size_t)gr * KTOT + kc0 + c4);
            As[c4 + 0][r] = v.x; As[c4 + 1][r] = v.y;
            As[c4 + 2][r] = v.z; As[c4 + 3][r] = v.w;
        }
        // load W tile
#pragma unroll
        for (int i = 0; i < KC / 8; ++i) {
            int f  = tid + i * 256;
            int kr = f >> 5;
            int c4 = (f & 31) * 4;
            *(float4*)(&Ws[kr][c4]) = *(const float4*)(W + (size_t)(kc0 + kr) * EH + c4);
        }
        __syncthreads();
#pragma unroll
        for (int k = 0; k < KC; ++k) {
            float a[8], w[8];
            *(float4*)&a[0] = *(const float4*)&As[k][tr * 8];
            *(float4*)&a[4] = *(const float4*)&As[k][tr * 8 + 4];
            *(float4*)&w[0] = *(const float4*)&Ws[k][tc * 8];
            *(float4*)&w[4] = *(const float4*)&Ws[k][tc * 8 + 4];
#pragma unroll
            for (int i = 0; i < 8; ++i)
#pragma unroll
                for (int j = 0; j < 8; ++j) acc[i][j] += a[i] * w[j];
        }
    }

    float bs[8];
    if constexpr (EPI != 2) {
#pragma unroll
        for (int j = 0; j < 8; ++j) bs[j] = bias[tc * 8 + j];
    }

    const int c0 = tc * 8;
#pragma unroll
    for (int i = 0; i < 8; ++i) {
        int r = r0 + tr * 8 + i;
        if (r >= M) continue;
        if constexpr (EPI == 0) {
            float4 v0, v1;
            v0.x = acc[i][0] + bs[0]; v0.y = acc[i][1] + bs[1];
            v0.z = acc[i][2] + bs[2]; v0.w = acc[i][3] + bs[3];
            v1.x = acc[i][4] + bs[4]; v1.y = acc[i][5] + bs[5];
            v1.z = acc[i][6] + bs[6]; v1.w = acc[i][7] + bs[7];
            *(float4*)(C + (size_t)r * EH + c0)     = v0;
            *(float4*)(C + (size_t)r * EH + c0 + 4) = v1;
        } else if constexpr (EPI == 1) {
            int u = gidx[r];
            const float* gp = gadd + (size_t)u * EH + c0;
            float4 p0 = *(const float4*)gp;
            float4 p1 = *(const float4*)(gp + 4);
            float4 v0, v1;
            v0.x = acc[i][0] + bs[0] + p0.x; v0.y = acc[i][1] + bs[1] + p0.y;
            v0.z = acc[i][2] + bs[2] + p0.z; v0.w = acc[i][3] + bs[3] + p0.w;
            v1.x = acc[i][4] + bs[4] + p1.x; v1.y = acc[i][5] + bs[5] + p1.y;
            v1.z = acc[i][6] + bs[6] + p1.z; v1.w = acc[i][7] + bs[7] + p1.w;
            *(float4*)(C + (size_t)r * EH + c0)     = v0;
            *(float4*)(C + (size_t)r * EH + c0 + 4) = v1;
        } else if constexpr (EPI == 2) {
            float4 v0, v1;
            v0.x = acc[i][0]; v0.y = acc[i][1]; v0.z = acc[i][2]; v0.w = acc[i][3];
            v1.x = acc[i][4]; v1.y = acc[i][5]; v1.z = acc[i][6]; v1.w = acc[i][7];
            *(float4*)(C + (size_t)r * EH + c0)     = v0;
            *(float4*)(C + (size_t)r * EH + c0 + 4) = v1;
            float* tp = acc_out + (size_t)gidx[r] * EH + c0;
#pragma unroll
            for (int j = 0; j < 8; ++j) atomicAdd(tp + j, acc[i][j]);
        } else {  // EPI == 3
            float* tp = acc_out + (size_t)gidx[r] * EH + c0;
#pragma unroll
            for (int j = 0; j < 8; ++j) atomicAdd(tp + j, acc[i][j] + bs[j]);
        }
    }
}

// h'[e] = relu(B[e] + W3_b + T[from[e]] - G[e^1])
__global__ void __launch_bounds__(256)
combine_kernel(const float* __restrict__ B, const float* __restrict__ T,
               const float* __restrict__ G, const int* __restrict__ from,
               const float* __restrict__ w3b, float* __restrict__ Hn)
{
    int idx = blockIdx.x * blockDim.x + threadIdx.x;
    if (idx >= NE * 32) return;
    int e = idx >> 5;
    int q = (idx & 31) << 2;
    int u = __ldg(&from[e]);
    float4 b = *(const float4*)(B + (size_t)e * EH + q);
    float4 t = *(const float4*)(T + (size_t)u * EH + q);
    float4 g = *(const float4*)(G + (size_t)(e ^ 1) * EH + q);
    float4 w = *(const float4*)(w3b + q);
    float4 r;
    r.x = fmaxf(b.x + w.x + t.x - g.x, 0.f);
    r.y = fmaxf(b.y + w.y + t.y - g.y, 0.f);
    r.z = fmaxf(b.z + w.z + t.z - g.z, 0.f);
    r.w = fmaxf(b.w + w.w + t.w - g.w, 0.f);
    *(float4*)(Hn + (size_t)e * EH + q) = r;
}

// out = relu(out + U1x)
__global__ void __launch_bounds__(256)
final_relu(float* __restrict__ out, const float* __restrict__ U1x)
{
    int idx = blockIdx.x * blockDim.x + threadIdx.x;
    if (idx >= NN * EH / 4) return;
    float4 a = ((const float4*)out)[idx];
    float4 b = ((const float4*)U1x)[idx];
    float4 r;
    r.x = fmaxf(a.x + b.x, 0.f);
    r.y = fmaxf(a.y + b.y, 0.f);
    r.z = fmaxf(a.z + b.z, 0.f);
    r.w = fmaxf(a.w + b.w, 0.f);
    ((float4*)out)[idx] = r;
}

extern "C" void kernel_launch(void* const* d_in, const int* in_sizes, int n_in,
                              void* d_out, int out_size)
{
    const float* nf  = (const float*)d_in[0];
    const float* ef  = (const float*)d_in[1];
    const float* eh0 = (const float*)d_in[2];
    const int*   edg = (const int*)  d_in[3];
    const float* W1w = (const float*)d_in[4];
    const float* W1b = (const float*)d_in[5];
    const float* W2w = (const float*)d_in[6];
    const float* W2b = (const float*)d_in[7];
    const float* W3w = (const float*)d_in[8];
    const float* W3b = (const float*)d_in[9];
    const float* U1w = (const float*)d_in[10];
    const float* U1b = (const float*)d_in[11];
    const float* U2w = (const float*)d_in[12];
    const float* U2b = (const float*)d_in[13];

    const int* from = edg;
    const int* to   = edg + NE;

    float *P, *U1x, *B, *G, *T, *H0, *H1;
    cudaGetSymbolAddress((void**)&P,   g_P);
    cudaGetSymbolAddress((void**)&U1x, g_U1);
    cudaGetSymbolAddress((void**)&B,   g_B);
    cudaGetSymbolAddress((void**)&G,   g_G);
    cudaGetSymbolAddress((void**)&T,   g_T);
    cudaGetSymbolAddress((void**)&H0,  g_H0);
    cudaGetSymbolAddress((void**)&H1,  g_H1);

    const int gnode = (NN + 127) / 128;
    const int gedge = (NE + 127) / 128;

    // loop-invariant precomputes
    gemm_tile<64, 0><<<gnode, 256>>>(nf, W1w, W1b, P,   NN, nullptr, nullptr, nullptr);
    gemm_tile<64, 0><<<gnode, 256>>>(nf, U1w, U1b, U1x, NN, nullptr, nullptr, nullptr);
    gemm_tile<16, 1><<<gedge, 256>>>(ef, W2w, W2b, B,   NE, from, P, nullptr);

    // message-passing steps
    const float* hc = eh0;
    float* hbuf[2] = {H0, H1};
    for (int s = 0; s < NSTEPS; ++s) {
        cudaMemsetAsync(T, 0, (size_t)NN * EH * sizeof(float));
        gemm_tile<128, 2><<<gedge, 256>>>(hc, W3w, nullptr, G, NE, from, nullptr, T);
        float* hn = hbuf[s & 1];
        combine_kernel<<<(NE * 32 + 255) / 256, 256>>>(B, T, G, from, W3b, hn);
        hc = hn;
    }

    // readout
    cudaMemsetAsync(d_out, 0, (size_t)NN * EH * sizeof(float));
    gemm_tile<128, 3><<<gedge, 256>>>(hc, U2w, U2b, nullptr, NE, to, nullptr, (float*)d_out);
    final_relu<<<(NN * EH / 4 + 255) / 256, 256>>>((float*)d_out, U1x);
}

// round 2
// speedup vs baseline: 1.5132x; 1.5132x over previous
#include <cuda_runtime.h>
#include <cstddef>

#define NN 100000
#define NE 600000
#define NF 64
#define EF 16
#define EH 128
#define NSTEPS 6

// ---- scratch (device globals; no allocation allowed) ----
__device__ float g_P [(size_t)NN * EH];   // nf@W1 + b1          (51 MB)
__device__ float g_U1[(size_t)NN * EH];   // nf@U1 + b1          (51 MB)
__device__ float g_B [(size_t)NE * EH];   // loop-invariant bias (307 MB)
__device__ float g_G [(size_t)NE * EH];   // h@W3                (307 MB)
__device__ float g_T [(size_t)NN * EH];   // segment_sum(g,from) (51 MB)
__device__ float g_H0[(size_t)NE * EH];   // h ping              (307 MB)
__device__ float g_H1[(size_t)NE * EH];   // h pong              (307 MB)

// ============================================================
// Tiled fp32 GEMM: C[M,128] = A[M,KTOT] @ W[KTOT,128]  (+epilogues)
// 256 threads, 128x128 tile, 8x8 per thread, K-chunks of min(KTOT,32).
// EPI 0: C = acc + bias                               (store)
// EPI 1: C = acc + bias + gadd[gidx[row]]             (store, gather-add)
// EPI 2: C = acc (store)  AND  atomicAdd acc_out[gidx[row]] += acc
// EPI 3: atomicAdd acc_out[gidx[row]] += acc + bias   (no store)
// ============================================================
template <int KTOT, int EPI>
__global__ void __launch_bounds__(256)
gemm_tile(const float* __restrict__ A, const float* __restrict__ W,
          const float* __restrict__ bias, float* __restrict__ C, int M,
          const int* __restrict__ gidx, const float* __restrict__ gadd,
          float* __restrict__ acc_out)
{
    constexpr int KC = (KTOT < 32) ? KTOT : 32;
    __shared__ float As[KC][132];   // [k][row], padded vs bank conflicts
    __shared__ float Ws[KC][128];   // [k][col]

    const int tid = threadIdx.x;
    const int tr  = tid >> 4;       // 0..15 (row group)
    const int tc  = tid & 15;       // 0..15 (col group)
    const int r0  = blockIdx.x * 128;

    float acc[8][8];
#pragma unroll
    for (int i = 0; i < 8; ++i)
#pragma unroll
        for (int j = 0; j < 8; ++j) acc[i][j] = 0.f;

    for (int kc0 = 0; kc0 < KTOT; kc0 += KC) {
        __syncthreads();
        // load A tile (transposed into smem)
#pragma unroll
        for (int i = 0; i < KC / 8; ++i) {
            int f  = tid + i * 256;
            int r  = f / (KC / 4);
            int c4 = (f % (KC / 4)) * 4;
            float4 v = make_float4(0.f, 0.f, 0.f, 0.f);
            int gr = r0 + r;
            if (gr < M) v = *(const float4*)(A + (size_t)gr * KTOT + kc0 + c4);
            As[c4 + 0][r] = v.x; As[c4 + 1][r] = v.y;
            As[c4 + 2][r] = v.z; As[c4 + 3][r] = v.w;
        }
        // load W tile
#pragma unroll
        for (int i = 0; i < KC / 8; ++i) {
            int f  = tid + i * 256;
            int kr = f >> 5;
            int c4 = (f & 31) * 4;
            *(float4*)(&Ws[kr][c4]) = *(const float4*)(W + (size_t)(kc0 + kr) * EH + c4);
        }
        __syncthreads();
#pragma unroll
        for (int k = 0; k < KC; ++k) {
            float a[8], w[8];
            *(float4*)&a[0] = *(const float4*)&As[k][tr * 8];
            *(float4*)&a[4] = *(const float4*)&As[k][tr * 8 + 4];
            *(float4*)&w[0] = *(const float4*)&Ws[k][tc * 8];
            *(float4*)&w[4] = *(const float4*)&Ws[k][tc * 8 + 4];
#pragma unroll
            for (int i = 0; i < 8; ++i)
#pragma unroll
                for (int j = 0; j < 8; ++j) acc[i][j] += a[i] * w[j];
        }
    }

    float bs[8];
    if constexpr (EPI != 2) {
#pragma unroll
        for (int j = 0; j < 8; ++j) bs[j] = bias[tc * 8 + j];
    }

    const int c0 = tc * 8;
#pragma unroll
    for (int i = 0; i < 8; ++i) {
        int r = r0 + tr * 8 + i;
        if (r >= M) continue;
        if constexpr (EPI == 0) {
            float4 v0, v1;
            v0.x = acc[i][0] + bs[0]; v0.y = acc[i][1] + bs[1];
            v0.z = acc[i][2] + bs[2]; v0.w = acc[i][3] + bs[3];
            v1.x = acc[i][4] + bs[4]; v1.y = acc[i][5] + bs[5];
            v1.z = acc[i][6] + bs[6]; v1.w = acc[i][7] + bs[7];
            *(float4*)(C + (size_t)r * EH + c0)     = v0;
            *(float4*)(C + (size_t)r * EH + c0 + 4) = v1;
        } else if constexpr (EPI == 1) {
            int u = gidx[r];
            const float* gp = gadd + (size_t)u * EH + c0;
            float4 p0 = *(const float4*)gp;
            float4 p1 = *(const float4*)(gp + 4);
            float4 v0, v1;
            v0.x = acc[i][0] + bs[0] + p0.x; v0.y = acc[i][1] + bs[1] + p0.y;
            v0.z = acc[i][2] + bs[2] + p0.z; v0.w = acc[i][3] + bs[3] + p0.w;
            v1.x = acc[i][4] + bs[4] + p1.x; v1.y = acc[i][5] + bs[5] + p1.y;
            v1.z = acc[i][6] + bs[6] + p1.z; v1.w = acc[i][7] + bs[7] + p1.w;
            *(float4*)(C + (size_t)r * EH + c0)     = v0;
            *(float4*)(C + (size_t)r * EH + c0 + 4) = v1;
        } else if constexpr (EPI == 2) {
            float4 v0, v1;
            v0.x = acc[i][0]; v0.y = acc[i][1]; v0.z = acc[i][2]; v0.w = acc[i][3];
            v1.x = acc[i][4]; v1.y = acc[i][5]; v1.z = acc[i][6]; v1.w = acc[i][7];
            *(float4*)(C + (size_t)r * EH + c0)     = v0;
            *(float4*)(C + (size_t)r * EH + c0 + 4) = v1;
            float* tp = acc_out + (size_t)gidx[r] * EH + c0;
#pragma unroll
            for (int j = 0; j < 8; ++j) atomicAdd(tp + j, acc[i][j]);
        } else {  // EPI == 3
            float* tp = acc_out + (size_t)gidx[r] * EH + c0;
#pragma unroll
            for (int j = 0; j < 8; ++j) atomicAdd(tp + j, acc[i][j] + bs[j]);
        }
    }
}

// h'[e] = relu(B[e] + W3_b + T[from[e]] - G[e^1])
__global__ void __launch_bounds__(256)
combine_kernel(const float* __restrict__ B, const float* __restrict__ T,
               const float* __restrict__ G, const int* __restrict__ from,
               const float* __restrict__ w3b, float* __restrict__ Hn)
{
    int idx = blockIdx.x * blockDim.x + threadIdx.x;
    if (idx >= NE * 32) return;
    int e = idx >> 5;
    int q = (idx & 31) << 2;
    int u = __ldg(&from[e]);
    float4 b = *(const float4*)(B + (size_t)e * EH + q);
    float4 t = *(const float4*)(T + (size_t)u * EH + q);
    float4 g = *(const float4*)(G + (size_t)(e ^ 1) * EH + q);
    float4 w = *(const float4*)(w3b + q);
    float4 r;
    r.x = fmaxf(b.x + w.x + t.x - g.x, 0.f);
    r.y = fmaxf(b.y + w.y + t.y - g.y, 0.f);
    r.z = fmaxf(b.z + w.z + t.z - g.z, 0.f);
    r.w = fmaxf(b.w + w.w + t.w - g.w, 0.f);
    *(float4*)(Hn + (size_t)e * EH + q) = r;
}

// out = relu(out + U1x)
__global__ void __launch_bounds__(256)
final_relu(float* __restrict__ out, const float* __restrict__ U1x)
{
    int idx = blockIdx.x * blockDim.x + threadIdx.x;
    if (idx >= NN * EH / 4) return;
    float4 a = ((const float4*)out)[idx];
    float4 b = ((const float4*)U1x)[idx];
    float4 r;
    r.x = fmaxf(a.x + b.x, 0.f);
    r.y = fmaxf(a.y + b.y, 0.f);
    r.z = fmaxf(a.z + b.z, 0.f);
    r.w = fmaxf(a.w + b.w, 0.f);
    ((float4*)out)[idx] = r;
}

extern "C" void kernel_launch(void* const* d_in, const int* in_sizes, int n_in,
                              void* d_out, int out_size)
{
    const float* nf  = (const float*)d_in[0];
    const float* ef  = (const float*)d_in[1];
    const float* eh0 = (const float*)d_in[2];
    const int*   edg = (const int*)  d_in[3];
    const float* W1w = (const float*)d_in[4];
    const float* W1b = (const float*)d_in[5];
    const float* W2w = (const float*)d_in[6];
    const float* W2b = (const float*)d_in[7];
    const float* W3w = (const float*)d_in[8];
    const float* W3b = (const float*)d_in[9];
    const float* U1w = (const float*)d_in[10];
    const float* U1b = (const float*)d_in[11];
    const float* U2w = (const float*)d_in[12];
    const float* U2b = (const float*)d_in[13];

    const int* from = edg;
    const int* to   = edg + NE;

    float *P, *U1x, *B, *G, *T, *H0, *H1;
    cudaGetSymbolAddress((void**)&P,   g_P);
    cudaGetSymbolAddress((void**)&U1x, g_U1);
    cudaGetSymbolAddress((void**)&B,   g_B);
    cudaGetSymbolAddress((void**)&G,   g_G);
    cudaGetSymbolAddress((void**)&T,   g_T);
    cudaGetSymbolAddress((void**)&H0,  g_H0);
    cudaGetSymbolAddress((void**)&H1,  g_H1);

    const int gnode = (NN + 127) / 128;
    const int gedge = (NE + 127) / 128;

    // loop-invariant precomputes
    gemm_tile<64, 0><<<gnode, 256>>>(nf, W1w, W1b, P,   NN, nullptr, nullptr, nullptr);
    gemm_tile<64, 0><<<gnode, 256>>>(nf, U1w, U1b, U1x, NN, nullptr, nullptr, nullptr);
    gemm_tile<16, 1><<<gedge, 256>>>(ef, W2w, W2b, B,   NE, from, P, nullptr);

    // message-passing steps
    const float* hc = eh0;
    float* hbuf[2] = {H0, H1};
    for (int s = 0; s < NSTEPS; ++s) {
        cudaMemsetAsync(T, 0, (size_t)NN * EH * sizeof(float));
        gemm_tile<128, 2><<<gedge, 256>>>(hc, W3w, nullptr, G, NE, from, nullptr, T);
        float* hn = hbuf[s & 1];
        combine_kernel<<<(NE * 32 + 255) / 256, 256>>>(B, T, G, from, W3b, hn);
        hc = hn;
    }

    // readout
    cudaMemsetAsync(d_out, 0, (size_t)NN * EH * sizeof(float));
    gemm_tile<128, 3><<<gedge, 256>>>(hc, U2w, U2b, nullptr, NE, to, nullptr, (float*)d_out);
    final_relu<<<(NN * EH / 4 + 255) / 256, 256>>>((float*)d_out, U1x);
}

// round 5
// speedup vs baseline: 3.0623x; 2.0238x over previous
#include <cuda_runtime.h>
#include <cstdint>
#include <cstddef>

#define NN 100000
#define NE 600000
#define NF 64
#define EF 16
#define EH 128
#define NSTEPS 6

// ---- scratch (device globals; no allocation allowed) ----
__device__ float g_P  [(size_t)NN * EH];   // nf@W1 + b1
__device__ float g_U1 [(size_t)NN * EH];   // nf@U1 + b1
__device__ float g_B  [(size_t)NE * EH];   // B' = P[from] + ef@W2 + b2 + b3
__device__ float g_G0 [(size_t)NE * EH];   // G ping
__device__ float g_G1 [(size_t)NE * EH];   // G pong
__device__ float g_T0 [(size_t)NN * EH];   // T ping
__device__ float g_T1 [(size_t)NN * EH];   // T pong
__device__ float g_W3t[128 * 128];         // W3^T (fp32)
__device__ float g_U2t[128 * 128];         // U2^T (fp32)
__device__ float g_cb [EH];                // W2_b + W3_b

// ================= helpers =================
__device__ __forceinline__ void split_tf32(float v, uint32_t& hi, uint32_t& lo) {
    uint32_t h;
    asm("cvt.rna.tf32.f32 %0, %1;" : "=r"(h) : "f"(v));
    float r = v - __uint_as_float(h);
    uint32_t l;
    asm("cvt.rna.tf32.f32 %0, %1;" : "=r"(l) : "f"(r));
    hi = h; lo = l;
}

__device__ __forceinline__ void mma8(float* c, const uint32_t* a,
                                     uint32_t b0, uint32_t b1) {
    asm volatile(
        "mma.sync.aligned.m16n8k8.row.col.f32.tf32.tf32.f32 "
        "{%0,%1,%2,%3}, {%4,%5,%6,%7}, {%8,%9}, {%0,%1,%2,%3};"
        : "+f"(c[0]), "+f"(c[1]), "+f"(c[2]), "+f"(c[3])
        : "r"(a[0]), "r"(a[1]), "r"(a[2]), "r"(a[3]), "r"(b0), "r"(b1));
}

__device__ __forceinline__ void red2(float* p, float x, float y) {
    asm volatile("red.global.add.v2.f32 [%0], {%1, %2};"
                 :: "l"(p), "f"(x), "f"(y) : "memory");
}

// transpose a 128x128 weight: out[n][k] = W[k][n]
__global__ void prep_w(const float* __restrict__ W, float* __restrict__ out) {
    int idx = blockIdx.x * 256 + threadIdx.x;   // 16384
    int k = idx >> 7, n = idx & 127;
    out[n * 128 + k] = W[idx];
}

__global__ void add_bias_vec(const float* __restrict__ a,
                             const float* __restrict__ b, float* __restrict__ o) {
    int i = threadIdx.x;
    if (i < EH) o[i] = a[i] + b[i];
}

// ============================================================
// Fused tf32x3 MMA GEMM over edges. Tile: 64 rows x 128 cols, K=128.
// A row e built on the fly:
//   FIRST:  a = relu(Bp[e])
//   else :  a = relu(Bp[e] + Tprev[from[e]] - Gprev[e^1])
// Epilogue:
//   STEP (!OUT): Gout[e] = acc ; red.v2 Acc[from[e]] += acc
//   OUT        : red.v2 Acc[to[e]] += acc + obias
// NE % 64 == 0 -> no bounds checks.
// ============================================================
static constexpr int AS_STRIDE = 132;
static constexpr size_t SM_AS = 0;
static constexpr size_t SM_WS = (size_t)64 * AS_STRIDE * 4;               // 33792
static constexpr size_t SM_TOT = SM_WS + (size_t)128 * AS_STRIDE * 4;     // 101376

template <bool FIRST, bool OUT>
__global__ void __launch_bounds__(256, 2)
gemm_fused(const float* __restrict__ Bp, const float* __restrict__ Tprev,
           const float* __restrict__ Gprev, const float* __restrict__ Wt,
           const int* __restrict__ from, const int* __restrict__ scat,
           const float* __restrict__ obias,
           float* __restrict__ Gout, float* __restrict__ Acc)
{
    extern __shared__ char smem[];
    float* As = (float*)(smem + SM_AS);   // [64][132]
    float* Ws = (float*)(smem + SM_WS);   // [128][132]  (W^T: [n][k])

    const int tid = threadIdx.x;
    const int r0  = blockIdx.x * 64;

    // ---- stage W^T (fp32) ----
    {
        const float4* src = (const float4*)Wt;
#pragma unroll
        for (int i = 0; i < 16; ++i) {
            int f = tid + i * 256;            // 0..4095 float4s
            int n = f >> 5, c4 = (f & 31) * 4;
            *(float4*)(Ws + n * AS_STRIDE + c4) = src[f];
        }
    }
    // ---- stage A with fused combine (fp32 in smem) ----
#pragma unroll
    for (int i = 0; i < 8; ++i) {
        int f   = tid + i * 256;              // 0..2047 float4s
        int row = f >> 5, c4 = (f & 31) * 4;
        int e   = r0 + row;
        float4 b = *(const float4*)(Bp + (size_t)e * EH + c4);
        float4 v;
        if constexpr (FIRST) {
            v.x = fmaxf(b.x, 0.f); v.y = fmaxf(b.y, 0.f);
            v.z = fmaxf(b.z, 0.f); v.w = fmaxf(b.w, 0.f);
        } else {
            int u = __ldg(&from[e]);
            float4 t = *(const float4*)(Tprev + (size_t)u * EH + c4);
            float4 g = *(const float4*)(Gprev + (size_t)(e ^ 1) * EH + c4);
            v.x = fmaxf(b.x + t.x - g.x, 0.f);
            v.y = fmaxf(b.y + t.y - g.y, 0.f);
            v.z = fmaxf(b.z + t.z - g.z, 0.f);
            v.w = fmaxf(b.w + t.w - g.w, 0.f);
        }
        *(float4*)(As + row * AS_STRIDE + c4) = v;
    }
    __syncthreads();

    // ---- MMA: warp (wr, wc): rows wr*32..+31, cols wc*32..+31 ----
    const int wid = tid >> 5, lane = tid & 31;
    const int gid = lane >> 2, tig = lane & 3;
    const int wr = wid & 1, wc = wid >> 1;
    const int ar0 = wr * 32, cn0 = wc * 32;

    float acc[2][4][4];
#pragma unroll
    for (int mt = 0; mt < 2; ++mt)
#pragma unroll
        for (int nt = 0; nt < 4; ++nt)
#pragma unroll
            for (int j = 0; j < 4; ++j) acc[mt][nt][j] = 0.f;

#pragma unroll
    for (int ks = 0; ks < 16; ++ks) {
        const int k0 = ks * 8;
        uint32_t ah[2][4], al[2][4];
#pragma unroll
        for (int mt = 0; mt < 2; ++mt) {
            const float* ap = As + (ar0 + mt * 16) * AS_STRIDE + k0;
            float av0 = ap[gid * AS_STRIDE + tig];
            float av1 = ap[(gid + 8) * AS_STRIDE + tig];
            float av2 = ap[gid * AS_STRIDE + tig + 4];
            float av3 = ap[(gid + 8) * AS_STRIDE + tig + 4];
            split_tf32(av0, ah[mt][0], al[mt][0]);
            split_tf32(av1, ah[mt][1], al[mt][1]);
            split_tf32(av2, ah[mt][2], al[mt][2]);
            split_tf32(av3, ah[mt][3], al[mt][3]);
        }
#pragma unroll
        for (int nt = 0; nt < 4; ++nt) {
            const float* bp = Ws + (cn0 + nt * 8 + gid) * AS_STRIDE + k0;
            uint32_t b0h, b0l, b1h, b1l;
            split_tf32(bp[tig],     b0h, b0l);
            split_tf32(bp[tig + 4], b1h, b1l);
            // hi*hi + lo*hi + hi*lo  (3xTF32)
            mma8(acc[0][nt], ah[0], b0h, b1h);
            mma8(acc[1][nt], ah[1], b0h, b1h);
            mma8(acc[0][nt], al[0], b0h, b1h);
            mma8(acc[1][nt], al[1], b0h, b1h);
            mma8(acc[0][nt], ah[0], b0l, b1l);
            mma8(acc[1][nt], ah[1], b0l, b1l);
        }
    }

    // ---- epilogue ----
#pragma unroll
    for (int mt = 0; mt < 2; ++mt) {
#pragma unroll
        for (int half = 0; half < 2; ++half) {
            const int r  = r0 + ar0 + mt * 16 + gid + half * 8;
            const int sc = __ldg(&scat[r]);
            float* ap = Acc + (size_t)sc * EH;
#pragma unroll
            for (int nt = 0; nt < 4; ++nt) {
                const int col = cn0 + nt * 8 + tig * 2;
                float x = acc[mt][nt][half * 2 + 0];
                float y = acc[mt][nt][half * 2 + 1];
                if constexpr (OUT) {
                    x += obias[col]; y += obias[col + 1];
                } else {
                    *(float2*)(Gout + (size_t)r * EH + col) = make_float2(x, y);
                }
                red2(ap + col, x, y);
            }
        }
    }
}

// ============================================================
// Scalar fp32 GEMM (small precompute GEMMs only)
// EPI 0: C = acc + bias ; EPI 1: C = acc + bias + gadd[gidx[row]]
// ============================================================
template <int KTOT, int EPI>
__global__ void __launch_bounds__(256)
gemm_tile(const float* __restrict__ A, const float* __restrict__ W,
          const float* __restrict__ bias, float* __restrict__ C, int M,
          const int* __restrict__ gidx, const float* __restrict__ gadd)
{
    constexpr int KC = (KTOT < 32) ? KTOT : 32;
    __shared__ float As[KC][132];
    __shared__ float Ws[KC][128];

    const int tid = threadIdx.x;
    const int tr  = tid >> 4;
    const int tc  = tid & 15;
    const int r0  = blockIdx.x * 128;

    float acc[8][8];
#pragma unroll
    for (int i = 0; i < 8; ++i)
#pragma unroll
        for (int j = 0; j < 8; ++j) acc[i][j] = 0.f;

    for (int kc0 = 0; kc0 < KTOT; kc0 += KC) {
        __syncthreads();
#pragma unroll
        for (int i = 0; i < KC / 8; ++i) {
            int f  = tid + i * 256;
            int r  = f / (KC / 4);
            int c4 = (f % (KC / 4)) * 4;
            float4 v = make_float4(0.f, 0.f, 0.f, 0.f);
            int gr = r0 + r;
            if (gr < M) v = *(const float4*)(A + (size_t)gr * KTOT + kc0 + c4);
            As[c4 + 0][r] = v.x; As[c4 + 1][r] = v.y;
            As[c4 + 2][r] = v.z; As[c4 + 3][r] = v.w;
        }
#pragma unroll
        for (int i = 0; i < KC / 8; ++i) {
            int f  = tid + i * 256;
            int kr = f >> 5;
            int c4 = (f & 31) * 4;
            *(float4*)(&Ws[kr][c4]) = *(const float4*)(W + (size_t)(kc0 + kr) * EH + c4);
        }
        __syncthreads();
#pragma unroll
        for (int k = 0; k < KC; ++k) {
            float a[8], w[8];
            *(float4*)&a[0] = *(const float4*)&As[k][tr * 8];
            *(float4*)&a[4] = *(const float4*)&As[k][tr * 8 + 4];
            *(float4*)&w[0] = *(const float4*)&Ws[k][tc * 8];
            *(float4*)&w[4] = *(const float4*)&Ws[k][tc * 8 + 4];
#pragma unroll
            for (int i = 0; i < 8; ++i)
#pragma unroll
                for (int j = 0; j < 8; ++j) acc[i][j] += a[i] * w[j];
        }
    }

    float bs[8];
#pragma unroll
    for (int j = 0; j < 8; ++j) bs[j] = bias[tc * 8 + j];

    const int c0 = tc * 8;
#pragma unroll
    for (int i = 0; i < 8; ++i) {
        int r = r0 + tr * 8 + i;
        if (r >= M) continue;
        if constexpr (EPI == 0) {
            float4 v0, v1;
            v0.x = acc[i][0] + bs[0]; v0.y = acc[i][1] + bs[1];
            v0.z = acc[i][2] + bs[2]; v0.w = acc[i][3] + bs[3];
            v1.x = acc[i][4] + bs[4]; v1.y = acc[i][5] + bs[5];
            v1.z = acc[i][6] + bs[6]; v1.w = acc[i][7] + bs[7];
            *(float4*)(C + (size_t)r * EH + c0)     = v0;
            *(float4*)(C + (size_t)r * EH + c0 + 4) = v1;
        } else {
            int u = gidx[r];
            const float* gp = gadd + (size_t)u * EH + c0;
            float4 p0 = *(const float4*)gp;
            float4 p1 = *(const float4*)(gp + 4);
            float4 v0, v1;
            v0.x = acc[i][0] + bs[0] + p0.x; v0.y = acc[i][1] + bs[1] + p0.y;
            v0.z = acc[i][2] + bs[2] + p0.z; v0.w = acc[i][3] + bs[3] + p0.w;
            v1.x = acc[i][4] + bs[4] + p1.x; v1.y = acc[i][5] + bs[5] + p1.y;
            v1.z = acc[i][6] + bs[6] + p1.z; v1.w = acc[i][7] + bs[7] + p1.w;
            *(float4*)(C + (size_t)r * EH + c0)     = v0;
            *(float4*)(C + (size_t)r * EH + c0 + 4) = v1;
        }
    }
}

// out = relu(out + U1x)
__global__ void __launch_bounds__(256)
final_relu(float* __restrict__ out, const float* __restrict__ U1x)
{
    int idx = blockIdx.x * blockDim.x + threadIdx.x;
    if (idx >= NN * EH / 4) return;
    float4 a = ((const float4*)out)[idx];
    float4 b = ((const float4*)U1x)[idx];
    float4 r;
    r.x = fmaxf(a.x + b.x, 0.f);
    r.y = fmaxf(a.y + b.y, 0.f);
    r.z = fmaxf(a.z + b.z, 0.f);
    r.w = fmaxf(a.w + b.w, 0.f);
    ((float4*)out)[idx] = r;
}

extern "C" void kernel_launch(void* const* d_in, const int* in_sizes, int n_in,
                              void* d_out, int out_size)
{
    const float* nf  = (const float*)d_in[0];
    const float* ef  = (const float*)d_in[1];
    const int*   edg = (const int*)  d_in[3];
    const float* W1w = (const float*)d_in[4];
    const float* W1b = (const float*)d_in[5];
    const float* W2w = (const float*)d_in[6];
    const float* W2b = (const float*)d_in[7];
    const float* W3w = (const float*)d_in[8];
    const float* W3b = (const float*)d_in[9];
    const float* U1w = (const float*)d_in[10];
    const float* U1b = (const float*)d_in[11];
    const float* U2w = (const float*)d_in[12];
    const float* U2b = (const float*)d_in[13];

    const int* from = edg;
    const int* to   = edg + NE;

    float *P, *U1x, *B, *G0, *G1, *T0, *T1, *W3t, *U2t, *cb;
    cudaGetSymbolAddress((void**)&P,   g_P);
    cudaGetSymbolAddress((void**)&U1x, g_U1);
    cudaGetSymbolAddress((void**)&B,   g_B);
    cudaGetSymbolAddress((void**)&G0,  g_G0);
    cudaGetSymbolAddress((void**)&G1,  g_G1);
    cudaGetSymbolAddress((void**)&T0,  g_T0);
    cudaGetSymbolAddress((void**)&T1,  g_T1);
    cudaGetSymbolAddress((void**)&W3t, g_W3t);
    cudaGetSymbolAddress((void**)&U2t, g_U2t);
    cudaGetSymbolAddress((void**)&cb,  g_cb);

    cudaFuncSetAttribute(gemm_fused<true,  false>,
                         cudaFuncAttributeMaxDynamicSharedMemorySize, (int)SM_TOT);
    cudaFuncSetAttribute(gemm_fused<false, false>,
                         cudaFuncAttributeMaxDynamicSharedMemorySize, (int)SM_TOT);
    cudaFuncSetAttribute(gemm_fused<false, true>,
                         cudaFuncAttributeMaxDynamicSharedMemorySize, (int)SM_TOT);

    const int gnode = (NN + 127) / 128;
    const int gedge128 = (NE + 127) / 128;
    const int gedge64  = NE / 64;          // 9375, exact

    // weight prep + combined bias
    prep_w<<<64, 256>>>(W3w, W3t);
    prep_w<<<64, 256>>>(U2w, U2t);
    add_bias_vec<<<1, 128>>>(W2b, W3b, cb);

    // loop-invariant precomputes
    gemm_tile<64, 0><<<gnode, 256>>>(nf, W1w, W1b, P,   NN, nullptr, nullptr);
    gemm_tile<64, 0><<<gnode, 256>>>(nf, U1w, U1b, U1x, NN, nullptr, nullptr);
    gemm_tile<16, 1><<<gedge128, 256>>>(ef, W2w, cb, B, NE, from, P);

    // buffers: step s output lives in buffer (s & 1)
    float* Gb[2] = {G0, G1};
    float* Tb[2] = {T0, T1};

    // s = 1: h1 = relu(B'), G = h1@W3, T = seg(G, from)  -> buffer 1
    cudaMemsetAsync(Tb[1], 0, (size_t)NN * EH * sizeof(float));
    gemm_fused<true, false><<<gedge64, 256, SM_TOT>>>(
        B, nullptr, nullptr, W3t, from, from, nullptr, Gb[1], Tb[1]);

    // s = 2..5: read buffer (s-1)&1, write buffer s&1
    for (int s = 2; s <= 5; ++s) {
        float* Gp = Gb[s & 1];
        float* Tp = Tb[s & 1];
        cudaMemsetAsync(Tp, 0, (size_t)NN * EH * sizeof(float));
        gemm_fused<false, false><<<gedge64, 256, SM_TOT>>>(
            B, Tb[(s - 1) & 1], Gb[(s - 1) & 1], W3t, from, from, nullptr, Gp, Tp);
    }

    // readout: h6 built on the fly from (T5, G5) = buffer 1; red into d_out by `to`
    cudaMemsetAsync(d_out, 0, (size_t)NN * EH * sizeof(float));
    gemm_fused<false, true><<<gedge64, 256, SM_TOT>>>(
        B, Tb[1], Gb[1], U2t, from, to, U2b, nullptr, (float*)d_out);

    final_relu<<<(NN * EH / 4 + 255) / 256, 256>>>((float*)d_out, U1x);
}

// round 6
// speedup vs baseline: 3.7934x; 1.2387x over previous
#include <cuda_runtime.h>
#include <cuda_bf16.h>
#include <cstdint>
#include <cstddef>

#define NN 100000
#define NE 600000
#define NF 64
#define EF 16
#define EH 128
#define NSTEPS 6

// ---- scratch (device globals; no allocation allowed) ----
__device__ float g_P  [(size_t)NN * EH];   // nf@W1 + b1
__device__ float g_U1 [(size_t)NN * EH];   // nf@U1 + b1
__device__ float g_B  [(size_t)NE * EH];   // B' = P[from] + ef@W2 + b2 + b3
__device__ float g_G0 [(size_t)NE * EH];   // G ping
__device__ float g_G1 [(size_t)NE * EH];   // G pong
__device__ float g_T0 [(size_t)NN * EH];   // T ping
__device__ float g_T1 [(size_t)NN * EH];   // T pong
__device__ uint32_t g_W3h[128 * 64];       // W3^T hi, bf16x2 packed along k
__device__ uint32_t g_W3l[128 * 64];       // W3^T lo
__device__ uint32_t g_U2h[128 * 64];       // U2^T hi
__device__ uint32_t g_U2l[128 * 64];       // U2^T lo
__device__ float g_cb [EH];                // W2_b + W3_b

// ================= helpers =================
__device__ __forceinline__ void mma16(float* c, const uint32_t* a,
                                      uint32_t b0, uint32_t b1) {
    asm volatile(
        "mma.sync.aligned.m16n8k16.row.col.f32.bf16.bf16.f32 "
        "{%0,%1,%2,%3}, {%4,%5,%6,%7}, {%8,%9}, {%0,%1,%2,%3};"
        : "+f"(c[0]), "+f"(c[1]), "+f"(c[2]), "+f"(c[3])
        : "r"(a[0]), "r"(a[1]), "r"(a[2]), "r"(a[3]), "r"(b0), "r"(b1));
}

__device__ __forceinline__ void red2(float* p, float x, float y) {
    asm volatile("red.global.add.v2.f32 [%0], {%1, %2};"
                 :: "l"(p), "f"(x), "f"(y) : "memory");
}

// split fp32 pair into bf16x2 hi + bf16x2 lo (packed 32-bit words)
__device__ __forceinline__ void split2(float x, float y, uint32_t& hi, uint32_t& lo) {
    __nv_bfloat162 h = __floats2bfloat162_rn(x, y);
    float2 hf = __bfloat1622float2(h);
    __nv_bfloat162 l = __floats2bfloat162_rn(x - hf.x, y - hf.y);
    hi = *(uint32_t*)&h;
    lo = *(uint32_t*)&l;
}

// transpose + bf16-split a 128x128 weight:
// out{h,l}[n][kp] holds bf16x2 of W[k=2kp][n], W[k=2kp+1][n]
__global__ void prep_w(const float* __restrict__ W,
                       uint32_t* __restrict__ oh, uint32_t* __restrict__ ol) {
    int idx = blockIdx.x * 256 + threadIdx.x;     // 8192
    int n = idx >> 6, kp = idx & 63;
    float v0 = W[(kp * 2 + 0) * 128 + n];
    float v1 = W[(kp * 2 + 1) * 128 + n];
    uint32_t hi, lo;
    split2(v0, v1, hi, lo);
    oh[idx] = hi;
    ol[idx] = lo;
}

__global__ void add_bias_vec(const float* __restrict__ a,
                             const float* __restrict__ b, float* __restrict__ o) {
    int i = threadIdx.x;
    if (i < EH) o[i] = a[i] + b[i];
}

// ============================================================
// Fused 3xBF16 MMA GEMM over edges. Tile: 64 rows x 128 cols, K=128.
// A row e built on the fly:
//   FIRST:  a = relu(Bp[e])
//   else :  a = relu(Bp[e] + Tprev[from[e]] - Gprev[e^1])
// then split into bf16 hi/lo tiles in smem.
// Epilogue:
//   STEP (!OUT): Gout[e] = acc ; red.v2 Acc[from[e]] += acc
//   OUT        : red.v2 Acc[to[e]] += acc + obias
// NE % 64 == 0 -> no bounds checks.
// ============================================================
static constexpr int STR = 68;                        // words (bf16x2) per row, padded
static constexpr int OFF_AH = 0;                      // [64][68]
static constexpr int OFF_AL = 64 * STR;               // 4352
static constexpr int OFF_WH = 2 * 64 * STR;           // 8704  [128][68]
static constexpr int OFF_WL = 2 * 64 * STR + 128 * STR;  // 17408
static constexpr int SM_WORDS = OFF_WL + 128 * STR;   // 26112
static constexpr size_t SM_TOT = (size_t)SM_WORDS * 4;  // 104448 B

template <bool FIRST, bool OUT>
__global__ void __launch_bounds__(256, 2)
gemm_fused(const float* __restrict__ Bp, const float* __restrict__ Tprev,
           const float* __restrict__ Gprev,
           const uint32_t* __restrict__ Wh, const uint32_t* __restrict__ Wl,
           const int* __restrict__ from, const int* __restrict__ scat,
           const float* __restrict__ obias,
           float* __restrict__ Gout, float* __restrict__ Acc)
{
    extern __shared__ uint32_t smem[];
    uint32_t* Ah = smem + OFF_AH;
    uint32_t* Al = smem + OFF_AL;
    uint32_t* Wsh = smem + OFF_WH;
    uint32_t* Wsl = smem + OFF_WL;

    const int tid = threadIdx.x;
    const int r0  = blockIdx.x * 64;

    // ---- stage W hi/lo (pre-split in gmem, compact [128][64] words) ----
#pragma unroll
    for (int i = 0; i < 8; ++i) {
        int f = tid + i * 256;               // 0..2047 uint4s over 8192 words
        int n = f >> 4, c = (f & 15) * 4;
        uint4 vh = *(const uint4*)(Wh + n * 64 + c);
        uint4 vl = *(const uint4*)(Wl + n * 64 + c);
        *(uint4*)(Wsh + n * STR + c) = vh;
        *(uint4*)(Wsl + n * STR + c) = vl;
    }
    // ---- stage A with fused combine + bf16 split ----
#pragma unroll
    for (int i = 0; i < 8; ++i) {
        int f   = tid + i * 256;             // 0..2047 float4s
        int row = f >> 5, c4 = (f & 31) * 4; // float col
        int e   = r0 + row;
        float4 b = *(const float4*)(Bp + (size_t)e * EH + c4);
        float4 v;
        if constexpr (FIRST) {
            v.x = fmaxf(b.x, 0.f); v.y = fmaxf(b.y, 0.f);
            v.z = fmaxf(b.z, 0.f); v.w = fmaxf(b.w, 0.f);
        } else {
            int u = __ldg(&from[e]);
            float4 t = *(const float4*)(Tprev + (size_t)u * EH + c4);
            float4 g = *(const float4*)(Gprev + (size_t)(e ^ 1) * EH + c4);
            v.x = fmaxf(b.x + t.x - g.x, 0.f);
            v.y = fmaxf(b.y + t.y - g.y, 0.f);
            v.z = fmaxf(b.z + t.z - g.z, 0.f);
            v.w = fmaxf(b.w + t.w - g.w, 0.f);
        }
        uint32_t h0, l0, h1, l1;
        split2(v.x, v.y, h0, l0);
        split2(v.z, v.w, h1, l1);
        int wb = row * STR + c4 / 2;
        Ah[wb] = h0; Ah[wb + 1] = h1;
        Al[wb] = l0; Al[wb + 1] = l1;
    }
    __syncthreads();

    // ---- MMA: warp (wr, wc): rows wr*32..+31, cols wc*32..+31 ----
    const int wid = tid >> 5, lane = tid & 31;
    const int gid = lane >> 2, tig = lane & 3;
    const int wr = wid & 1, wc = wid >> 1;
    const int ar0 = wr * 32, cn0 = wc * 32;

    float acc[2][4][4];
#pragma unroll
    for (int mt = 0; mt < 2; ++mt)
#pragma unroll
        for (int nt = 0; nt < 4; ++nt)
#pragma unroll
            for (int j = 0; j < 4; ++j) acc[mt][nt][j] = 0.f;

#pragma unroll
    for (int ks = 0; ks < 8; ++ks) {         // K = 8 steps * 16
        const int k0w = ks * 8;               // word offset (bf16x2)
        uint32_t ah[2][4], al[2][4];
#pragma unroll
        for (int mt = 0; mt < 2; ++mt) {
            int base = (ar0 + mt * 16 + gid) * STR + k0w + tig;
            ah[mt][0] = Ah[base];
            ah[mt][1] = Ah[base + 8 * STR];
            ah[mt][2] = Ah[base + 4];
            ah[mt][3] = Ah[base + 8 * STR + 4];
            al[mt][0] = Al[base];
            al[mt][1] = Al[base + 8 * STR];
            al[mt][2] = Al[base + 4];
            al[mt][3] = Al[base + 8 * STR + 4];
        }
#pragma unroll
        for (int nt = 0; nt < 4; ++nt) {
            int nb = (cn0 + nt * 8 + gid) * STR + k0w + tig;
            uint32_t bh0 = Wsh[nb], bh1 = Wsh[nb + 4];
            uint32_t bl0 = Wsl[nb], bl1 = Wsl[nb + 4];
            // hi*hi + lo*hi + hi*lo  (3xBF16)
            mma16(acc[0][nt], ah[0], bh0, bh1);
            mma16(acc[1][nt], ah[1], bh0, bh1);
            mma16(acc[0][nt], al[0], bh0, bh1);
            mma16(acc[1][nt], al[1], bh0, bh1);
            mma16(acc[0][nt], ah[0], bl0, bl1);
            mma16(acc[1][nt], ah[1], bl0, bl1);
        }
    }

    // ---- epilogue ----
#pragma unroll
    for (int mt = 0; mt < 2; ++mt) {
#pragma unroll
        for (int half = 0; half < 2; ++half) {
            const int r  = r0 + ar0 + mt * 16 + gid + half * 8;
            const int sc = __ldg(&scat[r]);
            float* ap = Acc + (size_t)sc * EH;
#pragma unroll
            for (int nt = 0; nt < 4; ++nt) {
                const int col = cn0 + nt * 8 + tig * 2;
                float x = acc[mt][nt][half * 2 + 0];
                float y = acc[mt][nt][half * 2 + 1];
                if constexpr (OUT) {
                    x += obias[col]; y += obias[col + 1];
                } else {
                    *(float2*)(Gout + (size_t)r * EH + col) = make_float2(x, y);
                }
                red2(ap + col, x, y);
            }
        }
    }
}

// ============================================================
// Scalar fp32 GEMM (small precompute GEMMs only)
// EPI 0: C = acc + bias ; EPI 1: C = acc + bias + gadd[gidx[row]]
// ============================================================
template <int KTOT, int EPI>
__global__ void __launch_bounds__(256)
gemm_tile(const float* __restrict__ A, const float* __restrict__ W,
          const float* __restrict__ bias, float* __restrict__ C, int M,
          const int* __restrict__ gidx, const float* __restrict__ gadd)
{
    constexpr int KC = (KTOT < 32) ? KTOT : 32;
    __shared__ float As[KC][132];
    __shared__ float Ws[KC][128];

    const int tid = threadIdx.x;
    const int tr  = tid >> 4;
    const int tc  = tid & 15;
    const int r0  = blockIdx.x * 128;

    float acc[8][8];
#pragma unroll
    for (int i = 0; i < 8; ++i)
#pragma unroll
        for (int j = 0; j < 8; ++j) acc[i][j] = 0.f;

    for (int kc0 = 0; kc0 < KTOT; kc0 += KC) {
        __syncthreads();
#pragma unroll
        for (int i = 0; i < KC / 8; ++i) {
            int f  = tid + i * 256;
            int r  = f / (KC / 4);
            int c4 = (f % (KC / 4)) * 4;
            float4 v = make_float4(0.f, 0.f, 0.f, 0.f);
            int gr = r0 + r;
            if (gr < M) v = *(const float4*)(A + (size_t)gr * KTOT + kc0 + c4);
            As[c4 + 0][r] = v.x; As[c4 + 1][r] = v.y;
            As[c4 + 2][r] = v.z; As[c4 + 3][r] = v.w;
        }
#pragma unroll
        for (int i = 0; i < KC / 8; ++i) {
            int f  = tid + i * 256;
            int kr = f >> 5;
            int c4 = (f & 31) * 4;
            *(float4*)(&Ws[kr][c4]) = *(const float4*)(W + (size_t)(kc0 + kr) * EH + c4);
        }
        __syncthreads();
#pragma unroll
        for (int k = 0; k < KC; ++k) {
            float a[8], w[8];
            *(float4*)&a[0] = *(const float4*)&As[k][tr * 8];
            *(float4*)&a[4] = *(const float4*)&As[k][tr * 8 + 4];
            *(float4*)&w[0] = *(const float4*)&Ws[k][tc * 8];
            *(float4*)&w[4] = *(const float4*)&Ws[k][tc * 8 + 4];
#pragma unroll
            for (int i = 0; i < 8; ++i)
#pragma unroll
                for (int j = 0; j < 8; ++j) acc[i][j] += a[i] * w[j];
        }
    }

    float bs[8];
#pragma unroll
    for (int j = 0; j < 8; ++j) bs[j] = bias[tc * 8 + j];

    const int c0 = tc * 8;
#pragma unroll
    for (int i = 0; i < 8; ++i) {
        int r = r0 + tr * 8 + i;
        if (r >= M) continue;
        if constexpr (EPI == 0) {
            float4 v0, v1;
            v0.x = acc[i][0] + bs[0]; v0.y = acc[i][1] + bs[1];
            v0.z = acc[i][2] + bs[2]; v0.w = acc[i][3] + bs[3];
            v1.x = acc[i][4] + bs[4]; v1.y = acc[i][5] + bs[5];
            v1.z = acc[i][6] + bs[6]; v1.w = acc[i][7] + bs[7];
            *(float4*)(C + (size_t)r * EH + c0)     = v0;
            *(float4*)(C + (size_t)r * EH + c0 + 4) = v1;
        } else {
            int u = gidx[r];
            const float* gp = gadd + (size_t)u * EH + c0;
            float4 p0 = *(const float4*)gp;
            float4 p1 = *(const float4*)(gp + 4);
            float4 v0, v1;
            v0.x = acc[i][0] + bs[0] + p0.x; v0.y = acc[i][1] + bs[1] + p0.y;
            v0.z = acc[i][2] + bs[2] + p0.z; v0.w = acc[i][3] + bs[3] + p0.w;
            v1.x = acc[i][4] + bs[4] + p1.x; v1.y = acc[i][5] + bs[5] + p1.y;
            v1.z = acc[i][6] + bs[6] + p1.z; v1.w = acc[i][7] + bs[7] + p1.w;
            *(float4*)(C + (size_t)r * EH + c0)     = v0;
            *(float4*)(C + (size_t)r * EH + c0 + 4) = v1;
        }
    }
}

// out = relu(out + U1x)
__global__ void __launch_bounds__(256)
final_relu(float* __restrict__ out, const float* __restrict__ U1x)
{
    int idx = blockIdx.x * blockDim.x + threadIdx.x;
    if (idx >= NN * EH / 4) return;
    float4 a = ((const float4*)out)[idx];
    float4 b = ((const float4*)U1x)[idx];
    float4 r;
    r.x = fmaxf(a.x + b.x, 0.f);
    r.y = fmaxf(a.y + b.y, 0.f);
    r.z = fmaxf(a.z + b.z, 0.f);
    r.w = fmaxf(a.w + b.w, 0.f);
    ((float4*)out)[idx] = r;
}

extern "C" void kernel_launch(void* const* d_in, const int* in_sizes, int n_in,
                              void* d_out, int out_size)
{
    const float* nf  = (const float*)d_in[0];
    const float* ef  = (const float*)d_in[1];
    const int*   edg = (const int*)  d_in[3];
    const float* W1w = (const float*)d_in[4];
    const float* W1b = (const float*)d_in[5];
    const float* W2w = (const float*)d_in[6];
    const float* W2b = (const float*)d_in[7];
    const float* W3w = (const float*)d_in[8];
    const float* W3b = (const float*)d_in[9];
    const float* U1w = (const float*)d_in[10];
    const float* U1b = (const float*)d_in[11];
    const float* U2w = (const float*)d_in[12];
    const float* U2b = (const float*)d_in[13];

    const int* from = edg;
    const int* to   = edg + NE;

    float *P, *U1x, *B, *G0, *G1, *T0, *T1, *cb;
    uint32_t *W3h, *W3l, *U2h, *U2l;
    cudaGetSymbolAddress((void**)&P,   g_P);
    cudaGetSymbolAddress((void**)&U1x, g_U1);
    cudaGetSymbolAddress((void**)&B,   g_B);
    cudaGetSymbolAddress((void**)&G0,  g_G0);
    cudaGetSymbolAddress((void**)&G1,  g_G1);
    cudaGetSymbolAddress((void**)&T0,  g_T0);
    cudaGetSymbolAddress((void**)&T1,  g_T1);
    cudaGetSymbolAddress((void**)&W3h, g_W3h);
    cudaGetSymbolAddress((void**)&W3l, g_W3l);
    cudaGetSymbolAddress((void**)&U2h, g_U2h);
    cudaGetSymbolAddress((void**)&U2l, g_U2l);
    cudaGetSymbolAddress((void**)&cb,  g_cb);

    cudaFuncSetAttribute(gemm_fused<true,  false>,
                         cudaFuncAttributeMaxDynamicSharedMemorySize, (int)SM_TOT);
    cudaFuncSetAttribute(gemm_fused<false, false>,
                         cudaFuncAttributeMaxDynamicSharedMemorySize, (int)SM_TOT);
    cudaFuncSetAttribute(gemm_fused<false, true>,
                         cudaFuncAttributeMaxDynamicSharedMemorySize, (int)SM_TOT);

    const int gnode = (NN + 127) / 128;
    const int gedge128 = (NE + 127) / 128;
    const int gedge64  = NE / 64;          // 9375, exact

    // weight prep + combined bias
    prep_w<<<32, 256>>>(W3w, W3h, W3l);
    prep_w<<<32, 256>>>(U2w, U2h, U2l);
    add_bias_vec<<<1, 128>>>(W2b, W3b, cb);

    // loop-invariant precomputes
    gemm_tile<64, 0><<<gnode, 256>>>(nf, W1w, W1b, P,   NN, nullptr, nullptr);
    gemm_tile<64, 0><<<gnode, 256>>>(nf, U1w, U1b, U1x, NN, nullptr, nullptr);
    gemm_tile<16, 1><<<gedge128, 256>>>(ef, W2w, cb, B, NE, from, P);

    // buffers: step s output lives in buffer (s & 1)
    float* Gb[2] = {G0, G1};
    float* Tb[2] = {T0, T1};

    // s = 1: h1 = relu(B'), G = h1@W3, T = seg(G, from)  -> buffer 1
    cudaMemsetAsync(Tb[1], 0, (size_t)NN * EH * sizeof(float));
    gemm_fused<true, false><<<gedge64, 256, SM_TOT>>>(
        B, nullptr, nullptr, W3h, W3l, from, from, nullptr, Gb[1], Tb[1]);

    // s = 2..5: read buffer (s-1)&1, write buffer s&1
    for (int s = 2; s <= 5; ++s) {
        float* Gp = Gb[s & 1];
        float* Tp = Tb[s & 1];
        cudaMemsetAsync(Tp, 0, (size_t)NN * EH * sizeof(float));
        gemm_fused<false, false><<<gedge64, 256, SM_TOT>>>(
            B, Tb[(s - 1) & 1], Gb[(s - 1) & 1], W3h, W3l, from, from, nullptr, Gp, Tp);
    }

    // readout: h6 built on the fly from (T5, G5) = buffer 1; red into d_out by `to`
    cudaMemsetAsync(d_out, 0, (size_t)NN * EH * sizeof(float));
    gemm_fused<false, true><<<gedge64, 256, SM_TOT>>>(
        B, Tb[1], Gb[1], U2h, U2l, from, to, U2b, nullptr, (float*)d_out);

    final_relu<<<(NN * EH / 4 + 255) / 256, 256>>>((float*)d_out, U1x);
}